// round 3
// baseline (speedup 1.0000x reference)
#include <cuda_runtime.h>
#include <math.h>

#define N_NODES 50000
#define N_EDGES 300000
#define DIM 256
#define N_RELS 500

// Scratch (device globals — never passed from host; R1 lesson: host-side
// reference to a __device__ symbol binds the host shadow array, and GB300
// ATS silently dereferences it as zeros)
__device__ float g_pre  [N_NODES * DIM];  // segment_sum(h[src]+emb[etype])
__device__ float g_gate [N_NODES * DIM];  // sigmoid(prev_h @ Ws + b)
__device__ float g_wcomb[2 * DIM * DIM];  // [Wn ; L] stacked (512 x 256)
__device__ int   g_indeg[N_NODES];
__device__ int   g_list [N_NODES];        // indeg==0 node ids
__device__ int   g_nfix;

// ---------------------------------------------------------------------------
// 1) zero scratch (g_pre, g_indeg, g_nfix)
// ---------------------------------------------------------------------------
__global__ void zero_kernel() {
    int i = blockIdx.x * blockDim.x + threadIdx.x;
    const int total4 = N_NODES * DIM / 4;
    float4 z = make_float4(0.f, 0.f, 0.f, 0.f);
    for (int idx = i; idx < total4; idx += gridDim.x * blockDim.x)
        reinterpret_cast<float4*>(g_pre)[idx] = z;
    if (i < N_NODES) g_indeg[i] = 0;
    if (i == 0) g_nfix = 0;
}

// ---------------------------------------------------------------------------
// 1b) stack Wn (rows 0..255) and loop_weight (rows 256..511) into g_wcomb
// ---------------------------------------------------------------------------
__global__ void prep_kernel(const float* __restrict__ Wn,
                            const float* __restrict__ L) {
    int i = blockIdx.x * blockDim.x + threadIdx.x;   // over DIM*DIM/4
    const int n4 = DIM * DIM / 4;
    if (i < n4) {
        reinterpret_cast<float4*>(g_wcomb)[i]      = reinterpret_cast<const float4*>(Wn)[i];
        reinterpret_cast<float4*>(g_wcomb)[n4 + i] = reinterpret_cast<const float4*>(L)[i];
    }
}

// ---------------------------------------------------------------------------
// 2) edge scatter: pre[dst] += h[src] + emb_rel[etype];  indeg[dst] += 1
// ---------------------------------------------------------------------------
__global__ void edge_kernel(const float* __restrict__ h,
                            const float* __restrict__ emb,
                            const int*   __restrict__ src,
                            const int*   __restrict__ dst,
                            const int*   __restrict__ etype) {
    long long tid = (long long)blockIdx.x * blockDim.x + threadIdx.x;
    int e = (int)(tid >> 6);           // 64 float4 per edge
    int j = (int)(tid & 63);
    if (e >= N_EDGES) return;
    int s = src[e];
    int d = dst[e];
    int r = etype[e];
    if (j == 0) atomicAdd(&g_indeg[d], 1);

    float4 hv = reinterpret_cast<const float4*>(h   + (size_t)s * DIM)[j];
    float4 ev = reinterpret_cast<const float4*>(emb + (size_t)r * DIM)[j];
    float4 v = make_float4(hv.x + ev.x, hv.y + ev.y, hv.z + ev.z, hv.w + ev.w);

    float* p = g_pre + (size_t)d * DIM + (size_t)j * 4;
    asm volatile("red.global.add.v4.f32 [%0], {%1, %2, %3, %4};"
                 :: "l"(p), "f"(v.x), "f"(v.y), "f"(v.z), "f"(v.w)
                 : "memory");
}

// ---------------------------------------------------------------------------
// 2b) compact list of indeg==0 nodes
// ---------------------------------------------------------------------------
__global__ void build_list_kernel() {
    int i = blockIdx.x * blockDim.x + threadIdx.x;
    if (i < N_NODES && g_indeg[i] == 0) {
        int slot = atomicAdd(&g_nfix, 1);
        g_list[slot] = i;
    }
}

// ---------------------------------------------------------------------------
// 3a) gate GEMM: g_gate = sigmoid(prev_h @ Ws + bias)
//     128x128 tile, BK=16, 8x8/thread.
// ---------------------------------------------------------------------------
__global__ __launch_bounds__(256)
void gate_gemm_kernel(const float* __restrict__ A_prev,
                      const float* __restrict__ B_skip,
                      const float* __restrict__ bias) {
    const int M = N_NODES, K = DIM, N = DIM;
    __shared__ float As[16][128];
    __shared__ float Bs[16][128];

    const int tid  = threadIdx.x;
    const int row0 = blockIdx.x * 128;
    const int col0 = blockIdx.y * 128;
    const int tx = tid & 15;
    const int ty = tid >> 4;
    const int arow = tid >> 2;
    const int acol = (tid & 3) * 4;
    const int brow = tid >> 5;
    const int bcol = (tid & 31) * 4;

    float acc[8][8];
    #pragma unroll
    for (int i = 0; i < 8; i++)
        #pragma unroll
        for (int j = 0; j < 8; j++) acc[i][j] = 0.f;

    for (int k0 = 0; k0 < K; k0 += 16) {
        #pragma unroll
        for (int i = 0; i < 2; i++) {
            int r = row0 + arow + i * 64;
            float4 v = (r < M)
                ? *reinterpret_cast<const float4*>(A_prev + (size_t)r * K + k0 + acol)
                : make_float4(0.f, 0.f, 0.f, 0.f);
            As[acol + 0][arow + i * 64] = v.x;
            As[acol + 1][arow + i * 64] = v.y;
            As[acol + 2][arow + i * 64] = v.z;
            As[acol + 3][arow + i * 64] = v.w;
        }
        #pragma unroll
        for (int i = 0; i < 2; i++) {
            int r = k0 + brow + i * 8;
            *reinterpret_cast<float4*>(&Bs[brow + i * 8][bcol]) =
                *reinterpret_cast<const float4*>(B_skip + (size_t)r * N + col0 + bcol);
        }
        __syncthreads();

        #pragma unroll
        for (int k = 0; k < 16; k++) {
            float4 a0 = *reinterpret_cast<const float4*>(&As[k][ty * 4]);
            float4 a1 = *reinterpret_cast<const float4*>(&As[k][64 + ty * 4]);
            float4 b0 = *reinterpret_cast<const float4*>(&Bs[k][tx * 4]);
            float4 b1 = *reinterpret_cast<const float4*>(&Bs[k][64 + tx * 4]);
            float ra[8] = {a0.x, a0.y, a0.z, a0.w, a1.x, a1.y, a1.z, a1.w};
            float rb[8] = {b0.x, b0.y, b0.z, b0.w, b1.x, b1.y, b1.z, b1.w};
            #pragma unroll
            for (int i = 0; i < 8; i++)
                #pragma unroll
                for (int j = 0; j < 8; j++)
                    acc[i][j] += ra[i] * rb[j];
        }
        __syncthreads();
    }

    #pragma unroll
    for (int ih = 0; ih < 2; ih++) {
        #pragma unroll
        for (int i = 0; i < 4; i++) {
            int r = row0 + ih * 64 + ty * 4 + i;
            if (r < M) {
                #pragma unroll
                for (int jh = 0; jh < 2; jh++) {
                    int c = col0 + jh * 64 + tx * 4;
                    float4 bs = *reinterpret_cast<const float4*>(bias + c);
                    float4 v;
                    v.x = 1.f / (1.f + __expf(-(acc[ih*4+i][jh*4+0] + bs.x)));
                    v.y = 1.f / (1.f + __expf(-(acc[ih*4+i][jh*4+1] + bs.y)));
                    v.z = 1.f / (1.f + __expf(-(acc[ih*4+i][jh*4+2] + bs.z)));
                    v.w = 1.f / (1.f + __expf(-(acc[ih*4+i][jh*4+3] + bs.w)));
                    *reinterpret_cast<float4*>(g_gate + (size_t)r * N + c) = v;
                }
            }
        }
    }
}

// ---------------------------------------------------------------------------
// 3b) main fused GEMM: acc = [pre*norm | h] @ [Wn ; L]   (K = 512)
//     epilogue: out = relu(gate*acc + (1-gate)*prev)
// ---------------------------------------------------------------------------
__global__ __launch_bounds__(256)
void main_gemm_kernel(const float* __restrict__ h,
                      const float* __restrict__ prevh,
                      const float* __restrict__ norm,
                      float* __restrict__ out) {
    const int M = N_NODES, N = DIM;
    __shared__ float As[16][128];
    __shared__ float Bs[16][128];

    const int tid  = threadIdx.x;
    const int row0 = blockIdx.x * 128;
    const int col0 = blockIdx.y * 128;
    const int tx = tid & 15;
    const int ty = tid >> 4;
    const int arow = tid >> 2;
    const int acol = (tid & 3) * 4;
    const int brow = tid >> 5;
    const int bcol = (tid & 31) * 4;

    float acc[8][8];
    #pragma unroll
    for (int i = 0; i < 8; i++)
        #pragma unroll
        for (int j = 0; j < 8; j++) acc[i][j] = 0.f;

    for (int k0 = 0; k0 < 2 * DIM; k0 += 16) {
        #pragma unroll
        for (int i = 0; i < 2; i++) {
            int r = row0 + arow + i * 64;
            float4 v = make_float4(0.f, 0.f, 0.f, 0.f);
            if (r < M) {
                if (k0 < DIM) {   // pre * norm[r]
                    v = *reinterpret_cast<const float4*>(g_pre + (size_t)r * DIM + k0 + acol);
                    float nm = norm[r];
                    v.x *= nm; v.y *= nm; v.z *= nm; v.w *= nm;
                } else {          // h
                    v = *reinterpret_cast<const float4*>(h + (size_t)r * DIM + (k0 - DIM) + acol);
                }
            }
            As[acol + 0][arow + i * 64] = v.x;
            As[acol + 1][arow + i * 64] = v.y;
            As[acol + 2][arow + i * 64] = v.z;
            As[acol + 3][arow + i * 64] = v.w;
        }
        #pragma unroll
        for (int i = 0; i < 2; i++) {
            int r = k0 + brow + i * 8;
            *reinterpret_cast<float4*>(&Bs[brow + i * 8][bcol]) =
                *reinterpret_cast<const float4*>(g_wcomb + (size_t)r * N + col0 + bcol);
        }
        __syncthreads();

        #pragma unroll
        for (int k = 0; k < 16; k++) {
            float4 a0 = *reinterpret_cast<const float4*>(&As[k][ty * 4]);
            float4 a1 = *reinterpret_cast<const float4*>(&As[k][64 + ty * 4]);
            float4 b0 = *reinterpret_cast<const float4*>(&Bs[k][tx * 4]);
            float4 b1 = *reinterpret_cast<const float4*>(&Bs[k][64 + tx * 4]);
            float ra[8] = {a0.x, a0.y, a0.z, a0.w, a1.x, a1.y, a1.z, a1.w};
            float rb[8] = {b0.x, b0.y, b0.z, b0.w, b1.x, b1.y, b1.z, b1.w};
            #pragma unroll
            for (int i = 0; i < 8; i++)
                #pragma unroll
                for (int j = 0; j < 8; j++)
                    acc[i][j] += ra[i] * rb[j];
        }
        __syncthreads();
    }

    #pragma unroll
    for (int ih = 0; ih < 2; ih++) {
        #pragma unroll
        for (int i = 0; i < 4; i++) {
            int r = row0 + ih * 64 + ty * 4 + i;
            if (r < M) {
                #pragma unroll
                for (int jh = 0; jh < 2; jh++) {
                    int c = col0 + jh * 64 + tx * 4;
                    float4 g  = *reinterpret_cast<const float4*>(g_gate + (size_t)r * N + c);
                    float4 pv = *reinterpret_cast<const float4*>(prevh  + (size_t)r * N + c);
                    float4 v;
                    v.x = fmaxf(g.x * acc[ih*4+i][jh*4+0] + (1.f - g.x) * pv.x, 0.f);
                    v.y = fmaxf(g.y * acc[ih*4+i][jh*4+1] + (1.f - g.y) * pv.y, 0.f);
                    v.z = fmaxf(g.z * acc[ih*4+i][jh*4+2] + (1.f - g.z) * pv.z, 0.f);
                    v.w = fmaxf(g.w * acc[ih*4+i][jh*4+3] + (1.f - g.w) * pv.w, 0.f);
                    *reinterpret_cast<float4*>(out + (size_t)r * N + c) = v;
                }
            }
        }
    }
}

// ---------------------------------------------------------------------------
// 4) fixup for indeg==0 rows (compacted list, ~124 expected):
//    agg == 0 there, so out = relu(gate*(h@Wev) + (1-gate)*prev)
// ---------------------------------------------------------------------------
__global__ void fixup_kernel(const float* __restrict__ h,
                             const float* __restrict__ Wev,
                             const float* __restrict__ prevh,
                             float* __restrict__ out) {
    __shared__ float hr[DIM];
    int t = threadIdx.x;                 // 256 threads, one output col each
    for (int li = blockIdx.x; li < g_nfix; li += gridDim.x) {
        int n = g_list[li];
        hr[t] = h[(size_t)n * DIM + t];
        __syncthreads();
        float acc = 0.f;
        #pragma unroll 8
        for (int k = 0; k < DIM; k++)
            acc += hr[k] * Wev[(size_t)k * DIM + t];
        float g  = g_gate[(size_t)n * DIM + t];
        float pv = prevh[(size_t)n * DIM + t];
        out[(size_t)n * DIM + t] = fmaxf(g * acc + (1.f - g) * pv, 0.f);
        __syncthreads();
    }
}

// ---------------------------------------------------------------------------
extern "C" void kernel_launch(void* const* d_in, const int* in_sizes, int n_in,
                              void* d_out, int out_size) {
    const float* h       = (const float*)d_in[0];
    const float* prev_h  = (const float*)d_in[1];
    const float* emb_rel = (const float*)d_in[2];
    const float* norm    = (const float*)d_in[3];
    const float* w_n     = (const float*)d_in[4];
    const float* w_loop  = (const float*)d_in[5];
    const float* w_ev    = (const float*)d_in[6];
    const float* w_skip  = (const float*)d_in[7];
    const float* b_skip  = (const float*)d_in[8];
    const int*   src     = (const int*)d_in[9];
    const int*   dst     = (const int*)d_in[10];
    const int*   etype   = (const int*)d_in[11];
    float* out = (float*)d_out;

    zero_kernel<<<2048, 256>>>();
    prep_kernel<<<(DIM * DIM / 4 + 255) / 256, 256>>>(w_n, w_loop);

    {
        long long threads = (long long)N_EDGES * 64;
        int blocks = (int)((threads + 255) / 256);
        edge_kernel<<<blocks, 256>>>(h, emb_rel, src, dst, etype);
    }
    build_list_kernel<<<(N_NODES + 255) / 256, 256>>>();

    {
        dim3 grid((N_NODES + 127) / 128, DIM / 128);
        gate_gemm_kernel<<<grid, 256>>>(prev_h, w_skip, b_skip);
        main_gemm_kernel<<<grid, 256>>>(h, prev_h, norm, out);
    }

    fixup_kernel<<<512, DIM>>>(h, w_ev, prev_h, out);
}

// round 5
// speedup vs baseline: 1.5008x; 1.5008x over previous
#include <cuda_runtime.h>
#include <cuda_fp16.h>
#include <math.h>
#include <stdint.h>

#define N_NODES 50000
#define N_EDGES 300000
#define DIM 256
#define N_RELS 500

// ---------------------------------------------------------------------------
// Device-global scratch (never passed from host — R1 lesson: host reference to
// a __device__ symbol binds the host shadow array; GB300 ATS reads it as junk)
// ---------------------------------------------------------------------------
__device__ float g_pre [N_NODES * DIM];   // segment_sum(h[src]+emb[etype])
__device__ float g_agg [N_NODES * DIM];   // D1 = [pre*norm | h] @ [Wn;L]^T
__device__ float g_gate[N_NODES * DIM];   // sigmoid(prev @ Ws^T + bias)
__device__ int   g_indeg[N_NODES];
__device__ int   g_list[N_NODES];
__device__ int   g_nfix;
// weights, transposed to [n][k] (K-major per output column), fp16
__device__ __half g_w1T[256 * 512];       // [Wn ; L]^T : n in [0,256), k in [0,512)
__device__ __half g_w2T[256 * 256];       // Ws^T

// ---------------------------------------------------------------------------
// helpers
// ---------------------------------------------------------------------------
__device__ __forceinline__ uint32_t smem_u32(const void* p) {
    uint32_t a;
    asm("{ .reg .u64 t; cvta.to.shared.u64 t, %1; cvt.u32.u64 %0, t; }"
        : "=r"(a) : "l"(p));
    return a;
}
// XOR swizzle: 16B-unit index within 128B row ^= row&7  (conflict-free LDSM)
#define SWZ(o) ((o) ^ (((o) >> 3) & 0x70))

#define LDSM4(r0, r1, r2, r3, addr) \
    asm volatile("ldmatrix.sync.aligned.m8n8.x4.shared.b16 {%0,%1,%2,%3}, [%4];" \
                 : "=r"(r0), "=r"(r1), "=r"(r2), "=r"(r3) : "r"(addr))

#define MMA16816(c, a, b0, b1) \
    asm volatile("mma.sync.aligned.m16n8k16.row.col.f32.f16.f16.f32 " \
                 "{%0,%1,%2,%3}, {%4,%5,%6,%7}, {%8,%9}, {%0,%1,%2,%3};" \
                 : "+f"((c)[0]), "+f"((c)[1]), "+f"((c)[2]), "+f"((c)[3]) \
                 : "r"((a)[0]), "r"((a)[1]), "r"((a)[2]), "r"((a)[3]), \
                   "r"(b0), "r"(b1))

// ---------------------------------------------------------------------------
// 1) zero scratch
// ---------------------------------------------------------------------------
__global__ void zero_kernel() {
    int i = blockIdx.x * blockDim.x + threadIdx.x;
    const int total4 = N_NODES * DIM / 4;
    float4 z = make_float4(0.f, 0.f, 0.f, 0.f);
    for (int idx = i; idx < total4; idx += gridDim.x * blockDim.x)
        reinterpret_cast<float4*>(g_pre)[idx] = z;
    if (i < N_NODES) g_indeg[i] = 0;
    if (i == 0) g_nfix = 0;
}

// ---------------------------------------------------------------------------
// 1b) weight prep: transpose + fp16 convert
// ---------------------------------------------------------------------------
__global__ void prep_kernel(const float* __restrict__ Wn,
                            const float* __restrict__ L,
                            const float* __restrict__ Ws) {
    int idx = blockIdx.x * blockDim.x + threadIdx.x;   // 131072 threads
    if (idx < 256 * 512) {
        int n = idx >> 9;
        int k = idx & 511;
        float w = (k < 256) ? Wn[k * 256 + n] : L[(k - 256) * 256 + n];
        g_w1T[idx] = __float2half_rn(w);
    }
    if (idx < 256 * 256) {
        int n = idx >> 8;
        int k = idx & 255;
        g_w2T[idx] = __float2half_rn(Ws[k * 256 + n]);
    }
}

// ---------------------------------------------------------------------------
// 2) edge scatter: pre[dst] += h[src] + emb_rel[etype];  indeg[dst] += 1
// ---------------------------------------------------------------------------
__global__ void edge_kernel(const float* __restrict__ h,
                            const float* __restrict__ emb,
                            const int*   __restrict__ src,
                            const int*   __restrict__ dst,
                            const int*   __restrict__ etype) {
    long long tid = (long long)blockIdx.x * blockDim.x + threadIdx.x;
    int e = (int)(tid >> 6);
    int j = (int)(tid & 63);
    if (e >= N_EDGES) return;
    int s = src[e];
    int d = dst[e];
    int r = etype[e];
    if (j == 0) atomicAdd(&g_indeg[d], 1);

    float4 hv = reinterpret_cast<const float4*>(h   + (size_t)s * DIM)[j];
    float4 ev = reinterpret_cast<const float4*>(emb + (size_t)r * DIM)[j];
    float4 v = make_float4(hv.x + ev.x, hv.y + ev.y, hv.z + ev.z, hv.w + ev.w);

    float* p = g_pre + (size_t)d * DIM + (size_t)j * 4;
    asm volatile("red.global.add.v4.f32 [%0], {%1, %2, %3, %4};"
                 :: "l"(p), "f"(v.x), "f"(v.y), "f"(v.z), "f"(v.w) : "memory");
}

// ---------------------------------------------------------------------------
// 2b) compact list of indeg==0 nodes
// ---------------------------------------------------------------------------
__global__ void build_list_kernel() {
    int i = blockIdx.x * blockDim.x + threadIdx.x;
    if (i < N_NODES && g_indeg[i] == 0) {
        int slot = atomicAdd(&g_nfix, 1);
        g_list[slot] = i;
    }
}

// ---------------------------------------------------------------------------
// staging: fp32 A rows -> (hi, lo) fp16 tiles (128 x 64), swizzled.
// thread t: row = t>>1, cols [(t&1)*32, +32)
// ---------------------------------------------------------------------------
__device__ __forceinline__ void stage_A(const float* __restrict__ src, int kbase,
                                        bool useNorm, const float* __restrict__ norm,
                                        int row0, __half* AsHi, __half* AsLo) {
    int rowL = threadIdx.x >> 1;
    int half = threadIdx.x & 1;
    int grow = row0 + rowL;
    bool ok = grow < N_NODES;
    float nm = 1.f;
    if (useNorm && ok) nm = __ldg(norm + grow);
    const float* s = src + (size_t)grow * DIM + kbase + half * 32;
    char* hB = reinterpret_cast<char*>(AsHi);
    char* lB = reinterpret_cast<char*>(AsLo);
    #pragma unroll
    for (int i = 0; i < 4; i++) {
        float4 v0, v1;
        if (ok) {
            v0 = *reinterpret_cast<const float4*>(s + i * 8);
            v1 = *reinterpret_cast<const float4*>(s + i * 8 + 4);
        } else {
            v0 = v1 = make_float4(0.f, 0.f, 0.f, 0.f);
        }
        float f[8] = {v0.x * nm, v0.y * nm, v0.z * nm, v0.w * nm,
                      v1.x * nm, v1.y * nm, v1.z * nm, v1.w * nm};
        uint32_t hw[4], lw[4];
        #pragma unroll
        for (int p = 0; p < 4; p++) {
            __half2 hh = __floats2half2_rn(f[2 * p], f[2 * p + 1]);
            float r0 = f[2 * p]     - __half2float(__low2half(hh));
            float r1 = f[2 * p + 1] - __half2float(__high2half(hh));
            __half2 ll = __floats2half2_rn(r0, r1);
            hw[p] = *reinterpret_cast<uint32_t*>(&hh);
            lw[p] = *reinterpret_cast<uint32_t*>(&ll);
        }
        uint32_t off = (uint32_t)(rowL * 128 + half * 64 + i * 16);
        uint32_t so = SWZ(off);
        *reinterpret_cast<uint4*>(hB + so) = make_uint4(hw[0], hw[1], hw[2], hw[3]);
        *reinterpret_cast<uint4*>(lB + so) = make_uint4(lw[0], lw[1], lw[2], lw[3]);
    }
}

// B^T tile (128 n-rows x 64 k), already fp16 in global, swizzled copy
__device__ __forceinline__ void stage_B(const __half* __restrict__ w, int KB,
                                        int kbase, int ncol0, __half* Bs) {
    int rowL = threadIdx.x >> 1;
    int half = threadIdx.x & 1;
    const uint4* s = reinterpret_cast<const uint4*>(
        w + (size_t)(ncol0 + rowL) * KB + kbase + half * 32);
    char* bB = reinterpret_cast<char*>(Bs);
    #pragma unroll
    for (int i = 0; i < 4; i++) {
        uint32_t off = (uint32_t)(rowL * 128 + half * 64 + i * 16);
        *reinterpret_cast<uint4*>(bB + SWZ(off)) = s[i];
    }
}

// ---------------------------------------------------------------------------
// 3) tensor-core GEMM (mma.sync fp16, A hi/lo split = 2 products, fp32 acc)
//    z=0: D2 = prev @ Ws^T (K=256) -> sigmoid(D2 + bias) -> g_gate
//    z=1: D1 = [pre*norm | h] @ [Wn;L]^T (K=512) -> g_agg (raw)
//    CTA tile 128x128, 8 warps (2M x 4N), warp tile 64x32.
// ---------------------------------------------------------------------------
__global__ __launch_bounds__(256)
void mma_gemm_kernel(const float* __restrict__ h,
                     const float* __restrict__ prevh,
                     const float* __restrict__ norm,
                     const float* __restrict__ bias) {
    __shared__ __half AsHi[128 * 64];
    __shared__ __half AsLo[128 * 64];
    __shared__ __half Bs  [128 * 64];

    const int tid  = threadIdx.x;
    const int lane = tid & 31;
    const int wid  = tid >> 5;
    const int warpM = wid >> 2;          // 0..1
    const int warpN = wid & 3;           // 0..3
    const int row0  = blockIdx.x * 128;
    const int ncol0 = blockIdx.y * 128;
    const bool isGate = (blockIdx.z == 0);
    const int nChunks = isGate ? 4 : 8;

    float acc[4][4][4];
    #pragma unroll
    for (int a = 0; a < 4; a++)
        #pragma unroll
        for (int b = 0; b < 4; b++)
            #pragma unroll
            for (int c = 0; c < 4; c++) acc[a][b][c] = 0.f;

    const uint32_t aHiB = smem_u32(AsHi);
    const uint32_t aLoB = smem_u32(AsLo);
    const uint32_t bB   = smem_u32(Bs);
    // ldmatrix lane-address components
    const int aRow  = (lane & 7) + ((lane >> 3) & 1) * 8;   // A: row within m16
    const int aColB = ((lane >> 4) & 1) * 16;               // A: k-half byte off
    const int bRowO = ((lane >> 4) & 1) * 8 + (lane & 7);   // B: n within 16-pair
    const int bColB = ((lane >> 3) & 1) * 16;               // B: k-half byte off

    for (int c = 0; c < nChunks; c++) {
        if (c) __syncthreads();
        if (isGate) {
            stage_A(prevh, c * 64, false, norm, row0, AsHi, AsLo);
            stage_B(g_w2T, 256, c * 64, ncol0, Bs);
        } else if (c < 4) {
            stage_A(g_pre, c * 64, true, norm, row0, AsHi, AsLo);
            stage_B(g_w1T, 512, c * 64, ncol0, Bs);
        } else {
            stage_A(h, (c - 4) * 64, false, norm, row0, AsHi, AsLo);
            stage_B(g_w1T, 512, c * 64, ncol0, Bs);
        }
        __syncthreads();

        #pragma unroll
        for (int k16 = 0; k16 < 4; k16++) {
            uint32_t bF[8];
            #pragma unroll
            for (int p = 0; p < 2; p++) {
                int n = warpN * 32 + p * 16 + bRowO;
                uint32_t ad = bB + SWZ((uint32_t)(n * 128 + k16 * 32 + bColB));
                LDSM4(bF[4 * p + 0], bF[4 * p + 1], bF[4 * p + 2], bF[4 * p + 3], ad);
            }
            uint32_t aH[4][4];
            #pragma unroll
            for (int mt = 0; mt < 4; mt++) {
                int r = warpM * 64 + mt * 16 + aRow;
                uint32_t ad = aHiB + SWZ((uint32_t)(r * 128 + k16 * 32 + aColB));
                LDSM4(aH[mt][0], aH[mt][1], aH[mt][2], aH[mt][3], ad);
            }
            #pragma unroll
            for (int mt = 0; mt < 4; mt++)
                #pragma unroll
                for (int nt = 0; nt < 4; nt++)
                    MMA16816(acc[mt][nt], aH[mt], bF[nt * 2], bF[nt * 2 + 1]);
            uint32_t aL[4][4];
            #pragma unroll
            for (int mt = 0; mt < 4; mt++) {
                int r = warpM * 64 + mt * 16 + aRow;
                uint32_t ad = aLoB + SWZ((uint32_t)(r * 128 + k16 * 32 + aColB));
                LDSM4(aL[mt][0], aL[mt][1], aL[mt][2], aL[mt][3], ad);
            }
            #pragma unroll
            for (int mt = 0; mt < 4; mt++)
                #pragma unroll
                for (int nt = 0; nt < 4; nt++)
                    MMA16816(acc[mt][nt], aL[mt], bF[nt * 2], bF[nt * 2 + 1]);
        }
    }

    // epilogue
    const int rbase = row0 + warpM * 64;
    const int cbase = ncol0 + warpN * 32;
    #pragma unroll
    for (int mt = 0; mt < 4; mt++) {
        #pragma unroll
        for (int nt = 0; nt < 4; nt++) {
            int gr = rbase + mt * 16 + (lane >> 2);
            int gc = cbase + nt * 8 + (lane & 3) * 2;
            if (isGate) {
                float b0 = bias[gc], b1 = bias[gc + 1];
                if (gr < N_NODES) {
                    float2 v;
                    v.x = 1.f / (1.f + __expf(-(acc[mt][nt][0] + b0)));
                    v.y = 1.f / (1.f + __expf(-(acc[mt][nt][1] + b1)));
                    *reinterpret_cast<float2*>(g_gate + (size_t)gr * DIM + gc) = v;
                }
                if (gr + 8 < N_NODES) {
                    float2 v;
                    v.x = 1.f / (1.f + __expf(-(acc[mt][nt][2] + b0)));
                    v.y = 1.f / (1.f + __expf(-(acc[mt][nt][3] + b1)));
                    *reinterpret_cast<float2*>(g_gate + (size_t)(gr + 8) * DIM + gc) = v;
                }
            } else {
                if (gr < N_NODES)
                    *reinterpret_cast<float2*>(g_agg + (size_t)gr * DIM + gc) =
                        make_float2(acc[mt][nt][0], acc[mt][nt][1]);
                if (gr + 8 < N_NODES)
                    *reinterpret_cast<float2*>(g_agg + (size_t)(gr + 8) * DIM + gc) =
                        make_float2(acc[mt][nt][2], acc[mt][nt][3]);
            }
        }
    }
}

// ---------------------------------------------------------------------------
// 4) blend: out = relu(gate*D1 + (1-gate)*prev)
// ---------------------------------------------------------------------------
__global__ void blend_kernel(const float* __restrict__ prevh,
                             float* __restrict__ out) {
    int i4 = blockIdx.x * blockDim.x + threadIdx.x;
    const int total4 = N_NODES * DIM / 4;
    if (i4 >= total4) return;
    float4 d1 = reinterpret_cast<const float4*>(g_agg)[i4];
    float4 g  = reinterpret_cast<const float4*>(g_gate)[i4];
    float4 pv = reinterpret_cast<const float4*>(prevh)[i4];
    float4 v;
    v.x = fmaxf(g.x * d1.x + (1.f - g.x) * pv.x, 0.f);
    v.y = fmaxf(g.y * d1.y + (1.f - g.y) * pv.y, 0.f);
    v.z = fmaxf(g.z * d1.z + (1.f - g.z) * pv.z, 0.f);
    v.w = fmaxf(g.w * d1.w + (1.f - g.w) * pv.w, 0.f);
    reinterpret_cast<float4*>(out)[i4] = v;
}

// ---------------------------------------------------------------------------
// 5) fixup for indeg==0 rows (~124): agg==0 and loop uses evolve weight.
//    out = relu(gate * (h@Wev) + (1-gate)*prev)  (exact fp32 matvec)
// ---------------------------------------------------------------------------
__global__ void fixup_kernel(const float* __restrict__ h,
                             const float* __restrict__ Wev,
                             const float* __restrict__ prevh,
                             float* __restrict__ out) {
    __shared__ float hr[DIM];
    int t = threadIdx.x;
    for (int li = blockIdx.x; li < g_nfix; li += gridDim.x) {
        int n = g_list[li];
        hr[t] = h[(size_t)n * DIM + t];
        __syncthreads();
        float accE = 0.f;
        #pragma unroll 8
        for (int k = 0; k < DIM; k++)
            accE += hr[k] * Wev[(size_t)k * DIM + t];
        float g  = g_gate[(size_t)n * DIM + t];
        float pv = prevh[(size_t)n * DIM + t];
        out[(size_t)n * DIM + t] = fmaxf(g * accE + (1.f - g) * pv, 0.f);
        __syncthreads();
    }
}

// ---------------------------------------------------------------------------
extern "C" void kernel_launch(void* const* d_in, const int* in_sizes, int n_in,
                              void* d_out, int out_size) {
    const float* h       = (const float*)d_in[0];
    const float* prev_h  = (const float*)d_in[1];
    const float* emb_rel = (const float*)d_in[2];
    const float* norm    = (const float*)d_in[3];
    const float* w_n     = (const float*)d_in[4];
    const float* w_loop  = (const float*)d_in[5];
    const float* w_ev    = (const float*)d_in[6];
    const float* w_skip  = (const float*)d_in[7];
    const float* b_skip  = (const float*)d_in[8];
    const int*   src     = (const int*)d_in[9];
    const int*   dst     = (const int*)d_in[10];
    const int*   etype   = (const int*)d_in[11];
    float* out = (float*)d_out;

    zero_kernel<<<2048, 256>>>();
    prep_kernel<<<512, 256>>>(w_n, w_loop, w_skip);

    {
        long long threads = (long long)N_EDGES * 64;
        int blocks = (int)((threads + 255) / 256);
        edge_kernel<<<blocks, 256>>>(h, emb_rel, src, dst, etype);
    }
    build_list_kernel<<<(N_NODES + 255) / 256, 256>>>();

    {
        dim3 grid((N_NODES + 127) / 128, 2, 2);   // y: N halves, z: gate|main
        mma_gemm_kernel<<<grid, 256>>>(h, prev_h, norm, b_skip);
    }

    {
        int total4 = N_NODES * DIM / 4;
        blend_kernel<<<(total4 + 255) / 256, 256>>>(prev_h, out);
    }
    fixup_kernel<<<512, DIM>>>(h, w_ev, prev_h, out);
}

// round 6
// speedup vs baseline: 1.6733x; 1.1149x over previous
#include <cuda_runtime.h>
#include <cuda_fp16.h>
#include <math.h>
#include <stdint.h>

#define N_NODES 50000
#define N_EDGES 300000
#define DIM 256
#define N_RELS 500

// ---------------------------------------------------------------------------
// Device-global scratch (never passed from host — R1 lesson: host reference to
// a __device__ symbol binds the host shadow array; GB300 ATS reads it as junk)
// ---------------------------------------------------------------------------
__device__ float g_pre [N_NODES * DIM];   // segment_sum(h[src]+emb[etype])
__device__ int   g_indeg[N_NODES];
__device__ int   g_list[N_NODES];
__device__ int   g_nfix;
// weights, transposed to [n][k] (K-major per output column), fp16
__device__ __half g_w1T[256 * 512];       // [Wn ; L]^T : n in [0,256), k in [0,512)
__device__ __half g_w2T[256 * 256];       // Ws^T

// ---------------------------------------------------------------------------
// helpers
// ---------------------------------------------------------------------------
__device__ __forceinline__ uint32_t smem_u32(const void* p) {
    uint32_t a;
    asm("{ .reg .u64 t; cvta.to.shared.u64 t, %1; cvt.u32.u64 %0, t; }"
        : "=r"(a) : "l"(p));
    return a;
}
// XOR swizzle: 16B-unit index within 128B row ^= row&7  (conflict-free LDSM)
#define SWZ(o) ((o) ^ (((o) >> 3) & 0x70))

#define LDSM4(r0, r1, r2, r3, addr) \
    asm volatile("ldmatrix.sync.aligned.m8n8.x4.shared.b16 {%0,%1,%2,%3}, [%4];" \
                 : "=r"(r0), "=r"(r1), "=r"(r2), "=r"(r3) : "r"(addr))

#define MMA16816(c, a, b0, b1) \
    asm volatile("mma.sync.aligned.m16n8k16.row.col.f32.f16.f16.f32 " \
                 "{%0,%1,%2,%3}, {%4,%5,%6,%7}, {%8,%9}, {%0,%1,%2,%3};" \
                 : "+f"((c)[0]), "+f"((c)[1]), "+f"((c)[2]), "+f"((c)[3]) \
                 : "r"((a)[0]), "r"((a)[1]), "r"((a)[2]), "r"((a)[3]), \
                   "r"(b0), "r"(b1))

// dynamic smem layout
#define OFF_AHI 0
#define OFF_ALO 16384
#define OFF_BS  32768
#define OFF_GS  49152          // gate fragments: uint32 [32][256] lane-interleaved
#define SMEM_TOT 81920         // 80 KB -> 2 CTAs/SM

// ---------------------------------------------------------------------------
// 1) zero scratch
// ---------------------------------------------------------------------------
__global__ void zero_kernel() {
    int i = blockIdx.x * blockDim.x + threadIdx.x;
    const int total4 = N_NODES * DIM / 4;
    float4 z = make_float4(0.f, 0.f, 0.f, 0.f);
    for (int idx = i; idx < total4; idx += gridDim.x * blockDim.x)
        reinterpret_cast<float4*>(g_pre)[idx] = z;
    if (i < N_NODES) g_indeg[i] = 0;
    if (i == 0) g_nfix = 0;
}

// ---------------------------------------------------------------------------
// 1b) weight prep: transpose + fp16 convert
// ---------------------------------------------------------------------------
__global__ void prep_kernel(const float* __restrict__ Wn,
                            const float* __restrict__ L,
                            const float* __restrict__ Ws) {
    int idx = blockIdx.x * blockDim.x + threadIdx.x;   // 131072 threads
    if (idx < 256 * 512) {
        int n = idx >> 9;
        int k = idx & 511;
        float w = (k < 256) ? Wn[k * 256 + n] : L[(k - 256) * 256 + n];
        g_w1T[idx] = __float2half_rn(w);
    }
    if (idx < 256 * 256) {
        int n = idx >> 8;
        int k = idx & 255;
        g_w2T[idx] = __float2half_rn(Ws[k * 256 + n]);
    }
}

// ---------------------------------------------------------------------------
// 2) edge scatter: pre[dst] += h[src] + emb_rel[etype];  indeg[dst] += 1
// ---------------------------------------------------------------------------
__global__ void edge_kernel(const float* __restrict__ h,
                            const float* __restrict__ emb,
                            const int*   __restrict__ src,
                            const int*   __restrict__ dst,
                            const int*   __restrict__ etype) {
    long long tid = (long long)blockIdx.x * blockDim.x + threadIdx.x;
    int e = (int)(tid >> 6);
    int j = (int)(tid & 63);
    if (e >= N_EDGES) return;
    int s = src[e];
    int d = dst[e];
    int r = etype[e];
    if (j == 0) atomicAdd(&g_indeg[d], 1);

    float4 hv = reinterpret_cast<const float4*>(h   + (size_t)s * DIM)[j];
    float4 ev = reinterpret_cast<const float4*>(emb + (size_t)r * DIM)[j];
    float4 v = make_float4(hv.x + ev.x, hv.y + ev.y, hv.z + ev.z, hv.w + ev.w);

    float* p = g_pre + (size_t)d * DIM + (size_t)j * 4;
    asm volatile("red.global.add.v4.f32 [%0], {%1, %2, %3, %4};"
                 :: "l"(p), "f"(v.x), "f"(v.y), "f"(v.z), "f"(v.w) : "memory");
}

// ---------------------------------------------------------------------------
// 2b) compact list of indeg==0 nodes
// ---------------------------------------------------------------------------
__global__ void build_list_kernel() {
    int i = blockIdx.x * blockDim.x + threadIdx.x;
    if (i < N_NODES && g_indeg[i] == 0) {
        int slot = atomicAdd(&g_nfix, 1);
        g_list[slot] = i;
    }
}

// ---------------------------------------------------------------------------
// staging: fp32 A rows -> (hi, lo) fp16 tiles (128 x 64), swizzled.
// thread t: row = t>>1, cols [(t&1)*32, +32)
// ---------------------------------------------------------------------------
__device__ __forceinline__ void stage_A(const float* __restrict__ src, int kbase,
                                        bool useNorm, const float* __restrict__ norm,
                                        int row0, char* hB, char* lB) {
    int rowL = threadIdx.x >> 1;
    int half = threadIdx.x & 1;
    int grow = row0 + rowL;
    bool ok = grow < N_NODES;
    float nm = 1.f;
    if (useNorm && ok) nm = __ldg(norm + grow);
    const float* s = src + (size_t)grow * DIM + kbase + half * 32;
    #pragma unroll
    for (int i = 0; i < 4; i++) {
        float4 v0, v1;
        if (ok) {
            v0 = *reinterpret_cast<const float4*>(s + i * 8);
            v1 = *reinterpret_cast<const float4*>(s + i * 8 + 4);
        } else {
            v0 = v1 = make_float4(0.f, 0.f, 0.f, 0.f);
        }
        float f[8] = {v0.x * nm, v0.y * nm, v0.z * nm, v0.w * nm,
                      v1.x * nm, v1.y * nm, v1.z * nm, v1.w * nm};
        uint32_t hw[4], lw[4];
        #pragma unroll
        for (int p = 0; p < 4; p++) {
            __half2 hh = __floats2half2_rn(f[2 * p], f[2 * p + 1]);
            float r0 = f[2 * p]     - __half2float(__low2half(hh));
            float r1 = f[2 * p + 1] - __half2float(__high2half(hh));
            __half2 ll = __floats2half2_rn(r0, r1);
            hw[p] = *reinterpret_cast<uint32_t*>(&hh);
            lw[p] = *reinterpret_cast<uint32_t*>(&ll);
        }
        uint32_t off = (uint32_t)(rowL * 128 + half * 64 + i * 16);
        uint32_t so = SWZ(off);
        *reinterpret_cast<uint4*>(hB + so) = make_uint4(hw[0], hw[1], hw[2], hw[3]);
        *reinterpret_cast<uint4*>(lB + so) = make_uint4(lw[0], lw[1], lw[2], lw[3]);
    }
}

// B^T tile (128 n-rows x 64 k), already fp16 in global, swizzled copy
__device__ __forceinline__ void stage_B(const __half* __restrict__ w, int KB,
                                        int kbase, int ncol0, char* bB) {
    int rowL = threadIdx.x >> 1;
    int half = threadIdx.x & 1;
    const uint4* s = reinterpret_cast<const uint4*>(
        w + (size_t)(ncol0 + rowL) * KB + kbase + half * 32);
    #pragma unroll
    for (int i = 0; i < 4; i++) {
        uint32_t off = (uint32_t)(rowL * 128 + half * 64 + i * 16);
        *reinterpret_cast<uint4*>(bB + SWZ(off)) = s[i];
    }
}

// ---------------------------------------------------------------------------
// 3) fully fused tensor-core kernel (mma.sync fp16, A hi/lo split, fp32 acc):
//    phase 1: D2 = prev @ Ws^T (K=256)  -> sigmoid(D2+bias) -> fp16 smem
//    phase 2: D1 = [pre*norm | h] @ [Wn;L]^T (K=512)
//    epilogue: out = relu(gate*D1 + (1-gate)*prev)  written directly
//    CTA tile 128x128, 8 warps (2M x 4N), warp tile 64x32.
// ---------------------------------------------------------------------------
__global__ __launch_bounds__(256, 2)
void fused_gemm_kernel(const float* __restrict__ h,
                       const float* __restrict__ prevh,
                       const float* __restrict__ norm,
                       const float* __restrict__ bias,
                       float* __restrict__ out) {
    extern __shared__ char smem[];
    char* aHiP = smem + OFF_AHI;
    char* aLoP = smem + OFF_ALO;
    char* bP   = smem + OFF_BS;
    uint32_t* Gs = reinterpret_cast<uint32_t*>(smem + OFF_GS);  // [32][256]

    const int tid  = threadIdx.x;
    const int lane = tid & 31;
    const int wid  = tid >> 5;
    const int warpM = wid >> 2;          // 0..1
    const int warpN = wid & 3;           // 0..3
    const int row0  = blockIdx.x * 128;
    const int ncol0 = blockIdx.y * 128;

    const uint32_t aHiB = smem_u32(aHiP);
    const uint32_t aLoB = smem_u32(aLoP);
    const uint32_t bB   = smem_u32(bP);
    // ldmatrix lane-address components
    const int aRow  = (lane & 7) + ((lane >> 3) & 1) * 8;
    const int aColB = ((lane >> 4) & 1) * 16;
    const int bRowO = ((lane >> 4) & 1) * 8 + (lane & 7);
    const int bColB = ((lane >> 3) & 1) * 16;

    const int rbase = row0 + warpM * 64;
    const int cbase = ncol0 + warpN * 32;

    float acc[4][4][4];

    // =============== phase 1: gate GEMM (K=256) ===============
    #pragma unroll
    for (int a = 0; a < 4; a++)
        #pragma unroll
        for (int b = 0; b < 4; b++)
            #pragma unroll
            for (int c = 0; c < 4; c++) acc[a][b][c] = 0.f;

    for (int c = 0; c < 4; c++) {
        if (c) __syncthreads();
        stage_A(prevh, c * 64, false, norm, row0, aHiP, aLoP);
        stage_B(g_w2T, 256, c * 64, ncol0, bP);
        __syncthreads();
        #pragma unroll
        for (int k16 = 0; k16 < 4; k16++) {
            uint32_t bF[8];
            #pragma unroll
            for (int p = 0; p < 2; p++) {
                int n = warpN * 32 + p * 16 + bRowO;
                LDSM4(bF[4*p+0], bF[4*p+1], bF[4*p+2], bF[4*p+3],
                      bB + SWZ((uint32_t)(n * 128 + k16 * 32 + bColB)));
            }
            uint32_t aF[4][4];
            #pragma unroll
            for (int mt = 0; mt < 4; mt++) {
                int r = warpM * 64 + mt * 16 + aRow;
                LDSM4(aF[mt][0], aF[mt][1], aF[mt][2], aF[mt][3],
                      aHiB + SWZ((uint32_t)(r * 128 + k16 * 32 + aColB)));
            }
            #pragma unroll
            for (int mt = 0; mt < 4; mt++)
                #pragma unroll
                for (int nt = 0; nt < 4; nt++)
                    MMA16816(acc[mt][nt], aF[mt], bF[nt*2], bF[nt*2+1]);
            #pragma unroll
            for (int mt = 0; mt < 4; mt++) {
                int r = warpM * 64 + mt * 16 + aRow;
                LDSM4(aF[mt][0], aF[mt][1], aF[mt][2], aF[mt][3],
                      aLoB + SWZ((uint32_t)(r * 128 + k16 * 32 + aColB)));
            }
            #pragma unroll
            for (int mt = 0; mt < 4; mt++)
                #pragma unroll
                for (int nt = 0; nt < 4; nt++)
                    MMA16816(acc[mt][nt], aF[mt], bF[nt*2], bF[nt*2+1]);
        }
    }

    // sigmoid(D2 + bias) -> Gs (fp16, thread-private fragments, lane-interleaved)
    #pragma unroll
    for (int mt = 0; mt < 4; mt++) {
        #pragma unroll
        for (int nt = 0; nt < 4; nt++) {
            int gc = cbase + nt * 8 + (lane & 3) * 2;
            float b0 = bias[gc], b1 = bias[gc + 1];
            float g0 = 1.f / (1.f + __expf(-(acc[mt][nt][0] + b0)));
            float g1 = 1.f / (1.f + __expf(-(acc[mt][nt][1] + b1)));
            float g2 = 1.f / (1.f + __expf(-(acc[mt][nt][2] + b0)));
            float g3 = 1.f / (1.f + __expf(-(acc[mt][nt][3] + b1)));
            __half2 p01 = __floats2half2_rn(g0, g1);
            __half2 p23 = __floats2half2_rn(g2, g3);
            Gs[((mt * 4 + nt) * 2 + 0) * 256 + tid] = *reinterpret_cast<uint32_t*>(&p01);
            Gs[((mt * 4 + nt) * 2 + 1) * 256 + tid] = *reinterpret_cast<uint32_t*>(&p23);
        }
    }

    // =============== phase 2: main GEMM (K=512) ===============
    #pragma unroll
    for (int a = 0; a < 4; a++)
        #pragma unroll
        for (int b = 0; b < 4; b++)
            #pragma unroll
            for (int c = 0; c < 4; c++) acc[a][b][c] = 0.f;

    for (int c = 0; c < 8; c++) {
        __syncthreads();
        if (c < 4) stage_A(g_pre, c * 64, true,  norm, row0, aHiP, aLoP);
        else       stage_A(h, (c - 4) * 64, false, norm, row0, aHiP, aLoP);
        stage_B(g_w1T, 512, c * 64, ncol0, bP);
        __syncthreads();
        #pragma unroll
        for (int k16 = 0; k16 < 4; k16++) {
            uint32_t bF[8];
            #pragma unroll
            for (int p = 0; p < 2; p++) {
                int n = warpN * 32 + p * 16 + bRowO;
                LDSM4(bF[4*p+0], bF[4*p+1], bF[4*p+2], bF[4*p+3],
                      bB + SWZ((uint32_t)(n * 128 + k16 * 32 + bColB)));
            }
            uint32_t aF[4][4];
            #pragma unroll
            for (int mt = 0; mt < 4; mt++) {
                int r = warpM * 64 + mt * 16 + aRow;
                LDSM4(aF[mt][0], aF[mt][1], aF[mt][2], aF[mt][3],
                      aHiB + SWZ((uint32_t)(r * 128 + k16 * 32 + aColB)));
            }
            #pragma unroll
            for (int mt = 0; mt < 4; mt++)
                #pragma unroll
                for (int nt = 0; nt < 4; nt++)
                    MMA16816(acc[mt][nt], aF[mt], bF[nt*2], bF[nt*2+1]);
            #pragma unroll
            for (int mt = 0; mt < 4; mt++) {
                int r = warpM * 64 + mt * 16 + aRow;
                LDSM4(aF[mt][0], aF[mt][1], aF[mt][2], aF[mt][3],
                      aLoB + SWZ((uint32_t)(r * 128 + k16 * 32 + aColB)));
            }
            #pragma unroll
            for (int mt = 0; mt < 4; mt++)
                #pragma unroll
                for (int nt = 0; nt < 4; nt++)
                    MMA16816(acc[mt][nt], aF[mt], bF[nt*2], bF[nt*2+1]);
        }
    }

    // =============== epilogue: blend + relu -> out ===============
    #pragma unroll
    for (int mt = 0; mt < 4; mt++) {
        #pragma unroll
        for (int nt = 0; nt < 4; nt++) {
            int gr = rbase + mt * 16 + (lane >> 2);
            int gc = cbase + nt * 8 + (lane & 3) * 2;
            uint32_t u01 = Gs[((mt * 4 + nt) * 2 + 0) * 256 + tid];
            uint32_t u23 = Gs[((mt * 4 + nt) * 2 + 1) * 256 + tid];
            float2 g01 = __half22float2(*reinterpret_cast<__half2*>(&u01));
            float2 g23 = __half22float2(*reinterpret_cast<__half2*>(&u23));
            if (gr < N_NODES) {
                float2 pv = *reinterpret_cast<const float2*>(prevh + (size_t)gr * DIM + gc);
                float2 v;
                v.x = fmaxf(g01.x * acc[mt][nt][0] + (1.f - g01.x) * pv.x, 0.f);
                v.y = fmaxf(g01.y * acc[mt][nt][1] + (1.f - g01.y) * pv.y, 0.f);
                *reinterpret_cast<float2*>(out + (size_t)gr * DIM + gc) = v;
            }
            if (gr + 8 < N_NODES) {
                float2 pv = *reinterpret_cast<const float2*>(prevh + (size_t)(gr + 8) * DIM + gc);
                float2 v;
                v.x = fmaxf(g23.x * acc[mt][nt][2] + (1.f - g23.x) * pv.x, 0.f);
                v.y = fmaxf(g23.y * acc[mt][nt][3] + (1.f - g23.y) * pv.y, 0.f);
                *reinterpret_cast<float2*>(out + (size_t)(gr + 8) * DIM + gc) = v;
            }
        }
    }
}

// ---------------------------------------------------------------------------
// 4) fixup for indeg==0 rows (~124): agg==0 and loop uses evolve weight.
//    out = relu(sig(prev@Ws + b) * (h@Wev) + (1-sig)*prev)   (exact fp32)
// ---------------------------------------------------------------------------
__global__ void fixup_kernel(const float* __restrict__ h,
                             const float* __restrict__ Wev,
                             const float* __restrict__ Ws,
                             const float* __restrict__ prevh,
                             const float* __restrict__ bias,
                             float* __restrict__ out) {
    __shared__ float hr[DIM];
    __shared__ float pr[DIM];
    int t = threadIdx.x;
    for (int li = blockIdx.x; li < g_nfix; li += gridDim.x) {
        int n = g_list[li];
        hr[t] = h[(size_t)n * DIM + t];
        pr[t] = prevh[(size_t)n * DIM + t];
        __syncthreads();
        float accE = 0.f, accS = 0.f;
        #pragma unroll 8
        for (int k = 0; k < DIM; k++) {
            accE += hr[k] * Wev[(size_t)k * DIM + t];
            accS += pr[k] * Ws[(size_t)k * DIM + t];
        }
        float g = 1.f / (1.f + __expf(-(accS + bias[t])));
        out[(size_t)n * DIM + t] = fmaxf(g * accE + (1.f - g) * pr[t], 0.f);
        __syncthreads();
    }
}

// ---------------------------------------------------------------------------
extern "C" void kernel_launch(void* const* d_in, const int* in_sizes, int n_in,
                              void* d_out, int out_size) {
    const float* h       = (const float*)d_in[0];
    const float* prev_h  = (const float*)d_in[1];
    const float* emb_rel = (const float*)d_in[2];
    const float* norm    = (const float*)d_in[3];
    const float* w_n     = (const float*)d_in[4];
    const float* w_loop  = (const float*)d_in[5];
    const float* w_ev    = (const float*)d_in[6];
    const float* w_skip  = (const float*)d_in[7];
    const float* b_skip  = (const float*)d_in[8];
    const int*   src     = (const int*)d_in[9];
    const int*   dst     = (const int*)d_in[10];
    const int*   etype   = (const int*)d_in[11];
    float* out = (float*)d_out;

    cudaFuncSetAttribute(fused_gemm_kernel,
                         cudaFuncAttributeMaxDynamicSharedMemorySize, SMEM_TOT);

    zero_kernel<<<2048, 256>>>();
    prep_kernel<<<512, 256>>>(w_n, w_loop, w_skip);

    {
        long long threads = (long long)N_EDGES * 64;
        int blocks = (int)((threads + 255) / 256);
        edge_kernel<<<blocks, 256>>>(h, emb_rel, src, dst, etype);
    }
    build_list_kernel<<<(N_NODES + 255) / 256, 256>>>();

    {
        dim3 grid((N_NODES + 127) / 128, 2);
        fused_gemm_kernel<<<grid, 256, SMEM_TOT>>>(h, prev_h, norm, b_skip, out);
    }

    fixup_kernel<<<512, DIM>>>(h, w_ev, w_skip, prev_h, b_skip, out);
}